// round 16
// baseline (speedup 1.0000x reference)
#include <cuda_runtime.h>
#include <mma.h>
#include <math.h>

#define NN 50000
#define EE 400000
#define TT 4
#define F0 128
#define F2 64

// ---------------- device scratch (no allocs allowed) ----------------
__device__ float g_scores0[TT * NN];
__device__ float g_scores1[TT * NN];
__device__ int   g_idx0[TT * 128];
__device__ float g_tv0[TT * 128];
__device__ int   g_idx1[TT * 64];
__device__ float g_tv1[TT * 64];
__device__ float g_inv[2];
__device__ float g_Q0s[TT][128 * 128];
__device__ float g_Q1s[TT][128 * 64];
__device__ float g_AX[TT][(size_t)NN * 128];
__device__ float g_h1[TT][(size_t)NN * 128];
__device__ float g_XW1[TT][(size_t)NN * 64];
__device__ int   g_rowptr[TT][NN + 1];
__device__ int   g_cursor[TT][NN];
__device__ int   g_csrc[TT][EE];
__device__ float g_csrw[TT][EE];

// ---------------- helpers ----------------
__device__ __forceinline__ unsigned sortable_u32(float f) {
    unsigned u = __float_as_uint(f);
    return (u & 0x80000000u) ? ~u : (u | 0x80000000u);
}

__device__ __forceinline__ void tf32split(float x, float& h, float& l) {
    unsigned uh, ul;
    asm("cvt.rna.tf32.f32 %0, %1;" : "=r"(uh) : "f"(x));
    h = __uint_as_float(uh);
    float r = x - h;
    asm("cvt.rna.tf32.f32 %0, %1;" : "=r"(ul) : "f"(r));
    l = __uint_as_float(ul);
}
__device__ __forceinline__ void tf32split4(float4 v, float4& h, float4& l) {
    tf32split(v.x, h.x, l.x); tf32split(v.y, h.y, l.y);
    tf32split(v.z, h.z, l.z); tf32split(v.w, h.w, l.w);
}

// ---------------- scorer norms ----------------
__global__ void norm_kernel(const float* __restrict__ s0, const float* __restrict__ s1,
                            float* __restrict__ inv) {
    const float* s = blockIdx.x ? s1 : s0;
    int t = threadIdx.x;
    float v = s[t]; v *= v;
    __shared__ float red[4];
    for (int o = 16; o; o >>= 1) v += __shfl_xor_sync(0xFFFFFFFFu, v, o);
    if ((t & 31) == 0) red[t >> 5] = v;
    __syncthreads();
    if (t == 0) inv[blockIdx.x] = rsqrtf(red[0] + red[1] + red[2] + red[3]);
}

// ---------------- scores for ALL layer-0 timesteps ----------------
__global__ __launch_bounds__(256) void scores0_all_kernel(
    const float* __restrict__ X, const float* __restrict__ scorer,
    const float* __restrict__ mask, const float* __restrict__ invp,
    float* __restrict__ out) {
    int warp = (blockIdx.x * blockDim.x + threadIdx.x) >> 5;
    int lane = threadIdx.x & 31;
    if (warp >= TT * NN) return;
    float4 x = reinterpret_cast<const float4*>(X)[(size_t)warp * 32 + lane];
    float4 s = reinterpret_cast<const float4*>(scorer)[lane];
    float d = x.x * s.x + x.y * s.y + x.z * s.z + x.w * s.w;
    for (int o = 16; o; o >>= 1) d += __shfl_xor_sync(0xFFFFFFFFu, d, o);
    if (lane == 0) out[warp] = d * invp[0] + mask[warp];
}

// ---------------- fused single-block topk, batched over t (blockIdx.x) ------
__global__ __launch_bounds__(1024) void topk_kernel(
    const float* __restrict__ scores_all, int k,
    int* __restrict__ idx_all, float* __restrict__ tv_all) {
    const float* scores = scores_all + (size_t)blockIdx.x * NN;
    int* idx_out = idx_all + blockIdx.x * k;
    float* tv_out = tv_all + blockIdx.x * k;
    __shared__ unsigned h1[1024];
    __shared__ unsigned csum[1024];
    __shared__ unsigned h2[64];
    __shared__ unsigned long long sk[4096];
    __shared__ int s_cb, s_kAbove, s_T16, s_cnt;
    int tid = threadIdx.x;
    h1[tid] = 0;
    if (tid < 64) h2[tid] = 0;
    if (tid == 0) s_cnt = 0;
    __syncthreads();

    const float4* s4 = reinterpret_cast<const float4*>(scores);
    for (int i = tid; i < NN / 4; i += 1024) {
        float4 v = s4[i];
        atomicAdd(&h1[sortable_u32(v.x) >> 22], 1u);
        atomicAdd(&h1[sortable_u32(v.y) >> 22], 1u);
        atomicAdd(&h1[sortable_u32(v.z) >> 22], 1u);
        atomicAdd(&h1[sortable_u32(v.w) >> 22], 1u);
    }
    __syncthreads();
    csum[tid] = h1[tid];
    __syncthreads();
    for (int off = 1; off < 1024; off <<= 1) {
        unsigned v = (tid + off < 1024) ? csum[tid + off] : 0u;
        __syncthreads();
        csum[tid] += v;
        __syncthreads();
    }
    unsigned above = (tid < 1023) ? csum[tid + 1] : 0u;
    if (csum[tid] >= (unsigned)k && above < (unsigned)k) { s_cb = tid; s_kAbove = (int)above; }
    __syncthreads();
    int cb = s_cb;
    unsigned kAbove = (unsigned)s_kAbove;

    for (int i = tid; i < NN / 4; i += 1024) {
        float4 v = s4[i];
        unsigned u;
        u = sortable_u32(v.x); if ((int)(u >> 22) == cb) atomicAdd(&h2[(u >> 16) & 63], 1u);
        u = sortable_u32(v.y); if ((int)(u >> 22) == cb) atomicAdd(&h2[(u >> 16) & 63], 1u);
        u = sortable_u32(v.z); if ((int)(u >> 22) == cb) atomicAdd(&h2[(u >> 16) & 63], 1u);
        u = sortable_u32(v.w); if ((int)(u >> 22) == cb) atomicAdd(&h2[(u >> 16) & 63], 1u);
    }
    __syncthreads();
    if (tid == 0) {
        unsigned run = kAbove;
        int f = 0;
        for (int b = 63; b >= 0; b--) {
            run += h2[b];
            if (run >= (unsigned)k) { f = b; break; }
        }
        s_T16 = (cb << 6) | f;
    }
    __syncthreads();
    int T16 = s_T16;

    for (int i = tid; i < NN / 4; i += 1024) {
        float4 v = s4[i];
        float vs[4] = {v.x, v.y, v.z, v.w};
#pragma unroll
        for (int c = 0; c < 4; c++) {
            unsigned u = sortable_u32(vs[c]);
            if ((int)(u >> 16) >= T16) {
                int p = atomicAdd(&s_cnt, 1);
                if (p < 4096) {
                    unsigned idx = (unsigned)(i * 4 + c);
                    sk[p] = ((unsigned long long)u << 32) |
                            (unsigned long long)(0xFFFFFFFFu - idx);
                }
            }
        }
    }
    __syncthreads();
    int cnt = s_cnt; if (cnt > 4096) cnt = 4096;
    int n = k; while (n < cnt) n <<= 1;
    for (int i = tid; i < n; i += 1024) if (i >= cnt) sk[i] = 0ULL;
    __syncthreads();
    for (int size = 2; size <= n; size <<= 1) {
        for (int stride = size >> 1; stride; stride >>= 1) {
            for (int i = tid; i < n; i += 1024) {
                int j = i ^ stride;
                if (j > i) {
                    bool asc = (i & size) != 0;
                    unsigned long long a = sk[i], b = sk[j];
                    if ((a > b) == asc) { sk[i] = b; sk[j] = a; }
                }
            }
            __syncthreads();
        }
    }
    if (tid < k) {
        unsigned long long key = sk[tid];
        int idx = (int)(0xFFFFFFFFu - (unsigned)(key & 0xFFFFFFFFu));
        if (idx < 0) idx = 0; if (idx >= NN) idx = NN - 1;
        idx_out[tid] = idx;
        tv_out[tid] = tanhf(scores[idx]);
    }
}

// ---------------- matrix GRU: one block per output column ----------------
template <int COLS>
__global__ __launch_bounds__(128) void gru_kernel(
    const float* __restrict__ X,
    const int* __restrict__ idx, const float* __restrict__ tv,
    const float* __restrict__ Wu, const float* __restrict__ Uu, const float* __restrict__ Bu,
    const float* __restrict__ Wr, const float* __restrict__ Ur, const float* __restrict__ Br,
    const float* __restrict__ Wh, const float* __restrict__ Uh, const float* __restrict__ Bh,
    const float* __restrict__ Qin, float* __restrict__ Qout) {
    __shared__ __align__(16) float zs[128];
    __shared__ __align__(16) float qs[128];
    __shared__ __align__(16) float rq[128];
    int c = blockIdx.x, r = threadIdx.x;
    zs[r] = X[(size_t)idx[c] * 128 + r] * tv[c];
    float q = Qin[r * COLS + c];
    qs[r] = q;
    __syncthreads();

    const float4* zr  = reinterpret_cast<const float4*>(zs);
    const float4* qr  = reinterpret_cast<const float4*>(qs);
    const float4* pwu = reinterpret_cast<const float4*>(Wu + r * 128);
    const float4* puu = reinterpret_cast<const float4*>(Uu + r * 128);
    const float4* pwr = reinterpret_cast<const float4*>(Wr + r * 128);
    const float4* pur = reinterpret_cast<const float4*>(Ur + r * 128);
    const float4* pwh = reinterpret_cast<const float4*>(Wh + r * 128);
    float au = 0.f, ar = 0.f, hw = 0.f;
#pragma unroll 8
    for (int i = 0; i < 32; i++) {
        float4 z4 = zr[i], q4 = qr[i];
        float4 a = pwu[i]; au += a.x * z4.x + a.y * z4.y + a.z * z4.z + a.w * z4.w;
        float4 b = puu[i]; au += b.x * q4.x + b.y * q4.y + b.z * q4.z + b.w * q4.w;
        float4 cc = pwr[i]; ar += cc.x * z4.x + cc.y * z4.y + cc.z * z4.z + cc.w * z4.w;
        float4 d = pur[i]; ar += d.x * q4.x + d.y * q4.y + d.z * q4.z + d.w * q4.w;
        float4 e = pwh[i]; hw += e.x * z4.x + e.y * z4.y + e.z * z4.z + e.w * z4.w;
    }
    float upd = 1.f / (1.f + expf(-(au + Bu[r * COLS + c])));
    float rst = 1.f / (1.f + expf(-(ar + Br[r * COLS + c])));
    rq[r] = rst * q;
    __syncthreads();
    const float4* puh = reinterpret_cast<const float4*>(Uh + r * 128);
    const float4* rq4 = reinterpret_cast<const float4*>(rq);
    float hu = 0.f;
#pragma unroll 8
    for (int i = 0; i < 32; i++) {
        float4 a = puh[i]; float4 v = rq4[i];
        hu += a.x * v.x + a.y * v.y + a.z * v.z + a.w * v.w;
    }
    float hcap = tanhf(hw + hu + Bh[r * COLS + c]);
    Qout[r * COLS + c] = (1.f - upd) * q + upd * hcap;
}

// ---- Tensor-core GEMM (3xTF32 split), batched over t (blockIdx.y) ----
// OUT[t] = X[t](NN x 128) @ Q[t](128 x BN).
// EPI: relu on output + fused scores1 = relu_row @ scorer * inv + mask.
template <int BN, bool EPI>
__global__ __launch_bounds__(256, 1) void gemm_tc_kernel(
    const float* __restrict__ Xall, const float* __restrict__ Qall,
    float* __restrict__ OUTall,
    const float* __restrict__ scorer, const float* __restrict__ invp,
    const float* __restrict__ maskall, float* __restrict__ scall) {
    using namespace nvcuda;
    constexpr int A_LD = 36;           // 32 + pad
    constexpr int B_LD = BN + 4;
    constexpr int C_LD = BN + 4;
    constexpr int WN = BN / 32;        // warps along N
    constexpr int WM = 8 / WN;         // warps along M
    constexpr int FM = (128 / WM) / 16;
    constexpr int FN = 2;
    extern __shared__ float smem[];
    float* Ah = smem;                  // [128][A_LD]
    float* Al = Ah + 128 * A_LD;
    float* Bh = Al + 128 * A_LD;       // [32][B_LD]
    float* Bl = Bh + 32 * B_LD;
    float* Csh = smem;                 // aliased after mma (guarded by syncs)
    __shared__ float scsh[128];

    const int tid = threadIdx.x;
    const int wid = tid >> 5;
    const int m0 = blockIdx.x * 128;
    const int t = blockIdx.y;
    const float* X = Xall + (size_t)t * NN * 128;
    const float* Q = Qall + (size_t)t * 128 * BN;
    float* OUT = OUTall + (size_t)t * NN * BN;

    if (EPI && tid < 128) scsh[tid] = scorer[tid];

    const int warp_m = wid / WN, warp_n = wid % WN;
    const int wrow = warp_m * (FM * 16);
    const int wcol = warp_n * 32;

    wmma::fragment<wmma::accumulator, 16, 16, 8, float> acc[FM][FN];
#pragma unroll
    for (int i = 0; i < FM; i++)
#pragma unroll
        for (int j = 0; j < FN; j++) wmma::fill_fragment(acc[i][j], 0.0f);

#pragma unroll
    for (int kc = 0; kc < 4; kc++) {           // K chunks of 32
        if (kc) __syncthreads();
        // load + split A chunk: [128][32]
        for (int f = tid; f < 128 * 8; f += 256) {
            int m = f >> 3, k4 = f & 7;
            float4 v = make_float4(0.f, 0.f, 0.f, 0.f);
            int gm = m0 + m;
            if (gm < NN) v = reinterpret_cast<const float4*>(X)[(size_t)gm * 32 + kc * 8 + k4];
            float4 h, l; tf32split4(v, h, l);
            *reinterpret_cast<float4*>(&Ah[m * A_LD + k4 * 4]) = h;
            *reinterpret_cast<float4*>(&Al[m * A_LD + k4 * 4]) = l;
        }
        // load + split B chunk: [32][BN]
        for (int f = tid; f < 32 * BN / 4; f += 256) {
            int k = f / (BN / 4), n4 = f % (BN / 4);
            float4 v = reinterpret_cast<const float4*>(Q)[(kc * 32 + k) * (BN / 4) + n4];
            float4 h, l; tf32split4(v, h, l);
            *reinterpret_cast<float4*>(&Bh[k * B_LD + n4 * 4]) = h;
            *reinterpret_cast<float4*>(&Bl[k * B_LD + n4 * 4]) = l;
        }
        __syncthreads();
#pragma unroll
        for (int ks = 0; ks < 4; ks++) {       // k-steps of 8
            int k0 = ks * 8;
            wmma::fragment<wmma::matrix_a, 16, 16, 8, wmma::precision::tf32, wmma::row_major> ah[FM], al[FM];
            wmma::fragment<wmma::matrix_b, 16, 16, 8, wmma::precision::tf32, wmma::row_major> bh[FN], bl[FN];
#pragma unroll
            for (int i = 0; i < FM; i++) {
                wmma::load_matrix_sync(ah[i], &Ah[(wrow + i * 16) * A_LD + k0], A_LD);
                wmma::load_matrix_sync(al[i], &Al[(wrow + i * 16) * A_LD + k0], A_LD);
            }
#pragma unroll
            for (int j = 0; j < FN; j++) {
                wmma::load_matrix_sync(bh[j], &Bh[k0 * B_LD + wcol + j * 16], B_LD);
                wmma::load_matrix_sync(bl[j], &Bl[k0 * B_LD + wcol + j * 16], B_LD);
            }
#pragma unroll
            for (int i = 0; i < FM; i++)
#pragma unroll
                for (int j = 0; j < FN; j++) {
                    wmma::mma_sync(acc[i][j], ah[i], bh[j], acc[i][j]);
                    wmma::mma_sync(acc[i][j], ah[i], bl[j], acc[i][j]);
                    wmma::mma_sync(acc[i][j], al[i], bh[j], acc[i][j]);
                }
        }
    }

    __syncthreads();   // all smem reads done; safe to alias as Csh
#pragma unroll
    for (int i = 0; i < FM; i++)
#pragma unroll
        for (int j = 0; j < FN; j++)
            wmma::store_matrix_sync(&Csh[(wrow + i * 16) * C_LD + wcol + j * 16],
                                    acc[i][j], C_LD, wmma::mem_row_major);
    __syncthreads();

    constexpr int NF4 = BN / 4;
    for (int f = tid; f < 128 * NF4; f += 256) {
        int m = f / NF4, n4 = f % NF4;
        float4 v = *reinterpret_cast<float4*>(&Csh[m * C_LD + n4 * 4]);
        if (EPI) {
            v.x = fmaxf(v.x, 0.f); v.y = fmaxf(v.y, 0.f);
            v.z = fmaxf(v.z, 0.f); v.w = fmaxf(v.w, 0.f);
            *reinterpret_cast<float4*>(&Csh[m * C_LD + n4 * 4]) = v;
        }
        int gm = m0 + m;
        if (gm < NN)
            reinterpret_cast<float4*>(OUT)[(size_t)gm * NF4 + n4] = v;
    }
    if (EPI) {
        __syncthreads();
        if (tid < 128) {
            int gm = m0 + tid;
            if (gm < NN) {
                const float4* cr = reinterpret_cast<const float4*>(&Csh[tid * C_LD]);
                const float4* sr = reinterpret_cast<const float4*>(scsh);
                float s = 0.f;
#pragma unroll 8
                for (int j4 = 0; j4 < 32; j4++) {
                    float4 c = cr[j4], sc = sr[j4];
                    s += c.x * sc.x + c.y * sc.y + c.z * sc.z + c.w * sc.w;
                }
                scall[(size_t)t * NN + gm] = s * invp[0] + maskall[(size_t)t * NN + gm];
            }
        }
    }
}

// ---------------- batched CSR build (all timesteps) ----------------
__global__ void deg_all_kernel(const int* __restrict__ dst, int* __restrict__ deg) {
    int i = blockIdx.x * blockDim.x + threadIdx.x;
    if (i < TT * EE) {
        int t = i / EE;
        atomicAdd(&deg[t * NN + dst[i]], 1);
    }
}

__global__ __launch_bounds__(1024) void scan_all_kernel(int* __restrict__ deg_all,
                                                        int* __restrict__ rowptr_all) {
    __shared__ int sums[1024];
    int* deg = deg_all + blockIdx.x * NN;
    int* rowptr = rowptr_all + blockIdx.x * (NN + 1);
    int tid = threadIdx.x;
    const int CH = (NN + 1023) / 1024;
    int s0 = tid * CH;
    int s = 0;
    for (int j = 0; j < CH; j++) {
        int i = s0 + j;
        if (i < NN) s += deg[i];
    }
    sums[tid] = s;
    __syncthreads();
    for (int off = 1; off < 1024; off <<= 1) {
        int v = (tid >= off) ? sums[tid - off] : 0;
        __syncthreads();
        sums[tid] += v;
        __syncthreads();
    }
    int run = (tid == 0) ? 0 : sums[tid - 1];
    for (int j = 0; j < CH; j++) {
        int i = s0 + j;
        if (i < NN) {
            int d = deg[i];
            rowptr[i] = run;
            deg[i] = run;
            run += d;
        }
    }
    if (tid == 1023) rowptr[NN] = sums[1023];
}

__global__ void fill_all_kernel(const int* __restrict__ dst, const int* __restrict__ src,
                                const float* __restrict__ ew,
                                int* __restrict__ cursor,
                                int* __restrict__ csrc, float* __restrict__ csrw) {
    int i = blockIdx.x * blockDim.x + threadIdx.x;
    if (i < TT * EE) {
        int t = i / EE;
        int p = atomicAdd(&cursor[t * NN + dst[i]], 1);
        csrc[t * EE + p] = src[i];
        csrw[t * EE + p] = ew[i];
    }
}

// ---------------- gather AX[t][d] = sum_e w_e * X[t][src_e]  (128 cols) ------
__global__ __launch_bounds__(256) void gatherAX_kernel(
    const float* __restrict__ Xall, const int* __restrict__ rowptr,
    const int* __restrict__ csrc, const float* __restrict__ csrw,
    float* __restrict__ AXall) {
    int warp = (blockIdx.x * blockDim.x + threadIdx.x) >> 5;
    int lane = threadIdx.x & 31;
    if (warp >= TT * NN) return;
    int t = warp / NN, node = warp - t * NN;
    const int* rp = rowptr + (size_t)t * (NN + 1) + node;
    const int* sp = csrc + (size_t)t * EE;
    const float* wp = csrw + (size_t)t * EE;
    const float4* X4 = reinterpret_cast<const float4*>(Xall + (size_t)t * NN * 128);
    int b = rp[0], e2 = rp[1];
    float4 acc = make_float4(0.f, 0.f, 0.f, 0.f);
    for (int j = b; j < e2; j++) {
        int s = sp[j];
        float w = wp[j];
        float4 v = X4[(size_t)s * 32 + lane];
        acc.x = fmaf(w, v.x, acc.x);
        acc.y = fmaf(w, v.y, acc.y);
        acc.z = fmaf(w, v.z, acc.z);
        acc.w = fmaf(w, v.w, acc.w);
    }
    reinterpret_cast<float4*>(AXall)[(size_t)warp * 32 + lane] = acc;
}

// ---------------- final gather: out[t][d] = relu(sum_e w_e XW1[t][src_e]) ----
__global__ __launch_bounds__(256) void gather64_kernel(
    const float* __restrict__ XWall, const int* __restrict__ rowptr,
    const int* __restrict__ csrc, const float* __restrict__ csrw,
    float* __restrict__ outall) {
    int warp = (blockIdx.x * blockDim.x + threadIdx.x) >> 5;
    int lane = threadIdx.x & 31;
    int f = warp * 2 + (lane >> 4);
    int cl = lane & 15;
    if (f >= TT * NN) return;
    int t = f / NN, node = f - t * NN;
    const int* rp = rowptr + (size_t)t * (NN + 1) + node;
    const int* sp = csrc + (size_t)t * EE;
    const float* wp = csrw + (size_t)t * EE;
    const float4* XW4 = reinterpret_cast<const float4*>(XWall + (size_t)t * NN * 64);
    int b = rp[0], e2 = rp[1];
    float4 acc = make_float4(0.f, 0.f, 0.f, 0.f);
    for (int j = b; j < e2; j++) {
        int s = sp[j];
        float w = wp[j];
        float4 v = XW4[(size_t)s * 16 + cl];
        acc.x = fmaf(w, v.x, acc.x);
        acc.y = fmaf(w, v.y, acc.y);
        acc.z = fmaf(w, v.z, acc.z);
        acc.w = fmaf(w, v.w, acc.w);
    }
    acc.x = fmaxf(acc.x, 0.f); acc.y = fmaxf(acc.y, 0.f);
    acc.z = fmaxf(acc.z, 0.f); acc.w = fmaxf(acc.w, 0.f);
    reinterpret_cast<float4*>(outall)[(size_t)f * 16 + cl] = acc;
}

// ---------------- host orchestration ----------------
extern "C" void kernel_launch(void* const* d_in, const int* in_sizes, int n_in,
                              void* d_out, int out_size) {
    const float* node_embs = (const float*)d_in[0];
    const float* mask      = (const float*)d_in[1];
    const int*   esrc      = (const int*)d_in[2];
    const int*   edst      = (const int*)d_in[3];
    const float* ew        = (const float*)d_in[4];
    const float* gcn_w0    = (const float*)d_in[5];
    const float* gcn_w1    = (const float*)d_in[6];
    const float* L0[10]; for (int i = 0; i < 10; i++) L0[i] = (const float*)d_in[7 + i];
    const float* L1[10]; for (int i = 0; i < 10; i++) L1[i] = (const float*)d_in[17 + i];
    float* out = (float*)d_out;

    float *scores0, *scores1, *tv0, *tv1, *inv, *q0s, *q1s, *ax, *h1, *xw1, *csrw;
    int *idx0, *idx1, *rowptr, *cursor, *csrc;
    cudaGetSymbolAddress((void**)&scores0, g_scores0);
    cudaGetSymbolAddress((void**)&scores1, g_scores1);
    cudaGetSymbolAddress((void**)&idx0,    g_idx0);
    cudaGetSymbolAddress((void**)&tv0,     g_tv0);
    cudaGetSymbolAddress((void**)&idx1,    g_idx1);
    cudaGetSymbolAddress((void**)&tv1,     g_tv1);
    cudaGetSymbolAddress((void**)&inv,     g_inv);
    cudaGetSymbolAddress((void**)&q0s,     g_Q0s);
    cudaGetSymbolAddress((void**)&q1s,     g_Q1s);
    cudaGetSymbolAddress((void**)&ax,      g_AX);
    cudaGetSymbolAddress((void**)&h1,      g_h1);
    cudaGetSymbolAddress((void**)&xw1,     g_XW1);
    cudaGetSymbolAddress((void**)&rowptr,  g_rowptr);
    cudaGetSymbolAddress((void**)&cursor,  g_cursor);
    cudaGetSymbolAddress((void**)&csrc,    g_csrc);
    cudaGetSymbolAddress((void**)&csrw,    g_csrw);

    // one-time host objects: 1 stream + 2 events (passing footprint)
    static cudaStream_t sB = nullptr;
    static cudaEvent_t evStart, evCSR;
    if (!sB) {
        cudaStreamCreateWithFlags(&sB, cudaStreamNonBlocking);
        cudaEventCreateWithFlags(&evStart, cudaEventDisableTiming);
        cudaEventCreateWithFlags(&evCSR,   cudaEventDisableTiming);
    }

    // dynamic smem: max(split tiles, C staging)
    size_t smA = (size_t)2 * 128 * 36 * sizeof(float);
    size_t sm128 = smA + (size_t)2 * 32 * 132 * sizeof(float);           // 70656
    size_t smC128 = (size_t)128 * 132 * sizeof(float);                   // 67584
    if (smC128 > sm128) sm128 = smC128;
    size_t sm64 = smA + (size_t)2 * 32 * 68 * sizeof(float);             // 54272
    size_t smC64 = (size_t)128 * 68 * sizeof(float);                     // 34816
    if (smC64 > sm64) sm64 = smC64;
    cudaFuncSetAttribute((const void*)gemm_tc_kernel<128, true>,
                         cudaFuncAttributeMaxDynamicSharedMemorySize, (int)sm128);
    cudaFuncSetAttribute((const void*)gemm_tc_kernel<64, false>,
                         cudaFuncAttributeMaxDynamicSharedMemorySize, (int)sm64);

    const int gblocks = (NN + 127) / 128;

    // ---- fork: sB builds CSR while origin does scores0/topk0/gru0 ----
    cudaEventRecord(evStart, 0);
    cudaStreamWaitEvent(sB, evStart, 0);

    cudaMemsetAsync(cursor, 0, (size_t)TT * NN * sizeof(int), sB);
    deg_all_kernel<<<(TT * EE + 255) / 256, 256, 0, sB>>>(edst, cursor);
    scan_all_kernel<<<TT, 1024, 0, sB>>>(cursor, rowptr);
    fill_all_kernel<<<(TT * EE + 255) / 256, 256, 0, sB>>>(edst, esrc, ew, cursor, csrc, csrw);
    cudaEventRecord(evCSR, sB);

    norm_kernel<<<2, 128>>>(L0[9], L1[9], inv);
    scores0_all_kernel<<<(TT * NN + 7) / 8, 256>>>(node_embs, L0[9], mask, inv, scores0);
    topk_kernel<<<TT, 1024>>>(scores0, 128, idx0, tv0);
    for (int t = 0; t < TT; t++) {
        const float* Xt   = node_embs + (size_t)t * NN * F0;
        const float* q0in = (t == 0) ? gcn_w0 : (q0s + (size_t)(t - 1) * 128 * 128);
        gru_kernel<128><<<128, 128>>>(Xt, idx0 + t * 128, tv0 + t * 128,
                                      L0[0], L0[1], L0[2], L0[3], L0[4],
                                      L0[5], L0[6], L0[7], L0[8],
                                      q0in, q0s + (size_t)t * 128 * 128);
    }

    // ---- join CSR, then the batched main chain on origin ----
    cudaStreamWaitEvent(0, evCSR, 0);

    // AX[t] = A(t) @ X(t)
    gatherAX_kernel<<<(TT * NN * 32 + 255) / 256, 256>>>(node_embs, rowptr, csrc, csrw, ax);

    // h1[t] = relu(AX[t] @ Q0[t]) + fused scores1
    gemm_tc_kernel<128, true><<<dim3(gblocks, TT), 256, sm128>>>(
        ax, q0s, h1, L1[9], inv + 1, mask, scores1);

    topk_kernel<<<TT, 1024>>>(scores1, 64, idx1, tv1);
    for (int t = 0; t < TT; t++) {
        const float* q1in = (t == 0) ? gcn_w1 : (q1s + (size_t)(t - 1) * 128 * 64);
        gru_kernel<64><<<64, 128>>>(h1 + (size_t)t * NN * 128, idx1 + t * 64, tv1 + t * 64,
                                    L1[0], L1[1], L1[2], L1[3], L1[4],
                                    L1[5], L1[6], L1[7], L1[8],
                                    q1in, q1s + (size_t)t * 128 * 64);
    }

    // XW1[t] = h1[t] @ Q1[t]
    gemm_tc_kernel<64, false><<<dim3(gblocks, TT), 256, sm64>>>(
        h1, q1s, xw1, nullptr, nullptr, nullptr, nullptr);

    // out[t] = relu(A(t) @ XW1[t])
    gather64_kernel<<<(((TT * NN + 1) / 2) * 32 + 255) / 256, 256>>>(
        xw1, rowptr, csrc, csrw, out);
}